// round 14
// baseline (speedup 1.0000x reference)
#include <cuda_runtime.h>
#include <cuda_fp16.h>
#include <math.h>

// ---------------- problem constants ----------------
#define NNODES 2048
#define SEQ    512
#define HID    256
#define NFEAT  9
#define NEDGE  65536
#define NLAY   3
#define STEPA  14

#define H   2048          // GRU hidden = NNODES
#define T   256           // GRU time steps = HID
#define GH  6144          // 3*H

#define NBLK 128          // persistent CTAs (co-resident)
#define IPB  16           // hidden units per CTA
#define NREP 4            // h publication replicas
#define SCAN_THREADS 512
#define PRE_THREADS  512

// dynamic SMEM layout for k_scan
#define WIHF_BYTES (8*48*32*16)              // 196608: next-layer wih fragments
#define SH_OFF     WIHF_BYTES                // 4096:   staged h (fp16)
#define SPT_OFF    (SH_OFF + 4096)           // 7680:   whh partials [2][48][20]
#define SPT2_OFF   (SPT_OFF + 7680)          // 2304:   gi partials [48][12]
#define SCAN_SMEM  (SPT2_OFF + 2304)         // 210688 total

// ---------------- scratch (device globals; no cudaMalloc allowed) ----------------
__device__ float    g_xs[NNODES*SEQ];
__device__ float    g_h0[NNODES*HID];
__device__ float    g_hagg[NNODES*HID];
__device__ float    g_deg[NNODES];
__device__ float    g_dinv[NNODES];
__device__ unsigned g_cnt[NNODES];
__device__ unsigned g_off[NNODES+1];
__device__ unsigned g_pos[NNODES];
__device__ int      g_srow[NEDGE];
__device__ float    g_snorm[NEDGE];
__device__ float    g_gi[2][T*GH];           // double-buffered input gates
__device__ __align__(16) __half g_htr[NREP][(T+1)*H];
__device__ unsigned g_bar[T+1];              // per-step arrival counters (monotonic)
__device__ unsigned g_pbar[8];               // phase barrier counters (preproc)

// ---------------- small helpers ----------------
__device__ __forceinline__ void bar_arrive(unsigned* p) {
    asm volatile("red.release.gpu.global.add.u32 [%0], 1;" :: "l"(p) : "memory");
}
__device__ __forceinline__ unsigned bar_ld_acq(const unsigned* p) {
    unsigned v;
    asm volatile("ld.acquire.gpu.global.u32 %0, [%1];" : "=r"(v) : "l"(p) : "memory");
    return v;
}
__device__ __forceinline__ void gbar(unsigned* ctr) {
    __syncthreads();
    if (threadIdx.x == 0) {
        bar_arrive(ctr);
        while (bar_ld_acq(ctr) < NBLK) {}
    }
    __syncthreads();
}
__device__ __forceinline__ void mma16816(float* d, const unsigned* a, const unsigned* b) {
    asm volatile("mma.sync.aligned.m16n8k16.row.col.f32.f16.f16.f32 "
                 "{%0,%1,%2,%3},{%4,%5,%6,%7},{%8,%9},{%0,%1,%2,%3};"
                 : "+f"(d[0]), "+f"(d[1]), "+f"(d[2]), "+f"(d[3])
                 : "r"(a[0]), "r"(a[1]), "r"(a[2]), "r"(a[3]),
                   "r"(b[0]), "r"(b[1]));
}
__device__ __forceinline__ unsigned pack_h2(float x, float y) {
    __half2 h = __floats2half2_rn(x, y);
    return *(unsigned*)&h;
}
__device__ __forceinline__ float fast_sigmoid(float x) {
    return __fdividef(1.0f, 1.0f + __expf(-x));
}
__device__ __forceinline__ float fast_tanh(float x) {
    return 1.0f - __fdividef(2.0f, __expf(2.0f * x) + 1.0f);
}
#define BAR_ARRIVE_N(id) asm volatile("bar.arrive %0, %1;" :: "r"(id), "r"(SCAN_THREADS))
#define BAR_SYNC_N(id)   asm volatile("bar.sync %0, %1;"   :: "r"(id), "r"(SCAN_THREADS) : "memory")
#define BAR3_ARRIVE()    asm volatile("bar.arrive 3, 288;")
#define BAR3_SYNC()      asm volatile("bar.sync 3, 288;" ::: "memory")

// ---------------- 0) replay-safe reset ----------------
__global__ void k_zero0() {
    int i = blockIdx.x * blockDim.x + threadIdx.x;   // 2048 threads
    if (i < 8) g_pbar[i] = 0u;
    if (i <= T) g_bar[i] = 0u;
    if (i < H) {
#pragma unroll
        for (int c = 0; c < NREP; c++) g_htr[c][i] = __float2half(0.0f);
    }
}

// ================= 1) fused preprocessing (persistent, 128 CTAs) =================
__global__ void __launch_bounds__(PRE_THREADS)
k_pre(const float* __restrict__ x,  const float* __restrict__ cw,
      const float* __restrict__ cb, const int*   __restrict__ ei,
      const float* __restrict__ ew, const float* __restrict__ gw,
      const float* __restrict__ gb) {
    __shared__ float As[16][64];
    __shared__ float Bs[16][68];
    __shared__ unsigned ps[512];
    const int b = blockIdx.x, tid = threadIdx.x;
    const int gt = b * PRE_THREADS + tid;
    const int GT = NBLK * PRE_THREADS;

    // ---- P0: 1x1 conv + deg=1 + cnt=0 ----
    {
        float bias = cb[0];
        float w[NFEAT];
#pragma unroll
        for (int f = 0; f < NFEAT; f++) w[f] = cw[f];
        const int n4 = NNODES * SEQ / 4;
        const float4* X = (const float4*)x;
        for (int i = gt; i < n4; i += GT) {
            float4 acc = make_float4(bias, bias, bias, bias);
#pragma unroll
            for (int f = 0; f < NFEAT; f++) {
                float4 v = X[(size_t)f * n4 + i];
                acc.x = fmaf(w[f], v.x, acc.x); acc.y = fmaf(w[f], v.y, acc.y);
                acc.z = fmaf(w[f], v.z, acc.z); acc.w = fmaf(w[f], v.w, acc.w);
            }
            ((float4*)g_xs)[i] = acc;
        }
        for (int i = gt; i < NNODES; i += GT) { g_deg[i] = 1.0f; g_cnt[i] = 0u; }
    }
    gbar(&g_pbar[0]);

    // ---- P1: degree + histogram atomics + h0 = xs @ gcn_w ----
    for (int e = gt; e < NEDGE; e += GT) {
        int col = ei[NEDGE + e];
        atomicAdd(&g_deg[col], ew[e]);
        atomicAdd(&g_cnt[col], 1u);
    }
    {
        const int bm = (b >> 2) * 64, bn = (b & 3) * 64;
        const int tx = tid & 15, ty = tid >> 4;
        float acc[2][4] = {};
        for (int k0 = 0; k0 < SEQ; k0 += 16) {
            {
                int ar = tid >> 3, ac = (tid & 7) * 2;
                float2 v = *(const float2*)&g_xs[(bm + ar) * SEQ + k0 + ac];
                As[ac][ar] = v.x; As[ac + 1][ar] = v.y;
            }
            {
                int br = tid >> 5, bc = (tid & 31) * 2;
                float2 v = *(const float2*)&gw[(k0 + br) * HID + bn + bc];
                Bs[br][bc] = v.x; Bs[br][bc + 1] = v.y;
            }
            __syncthreads();
#pragma unroll
            for (int kk = 0; kk < 16; kk++) {
                float a0 = As[kk][ty * 2], a1 = As[kk][ty * 2 + 1];
                float4 bb = *(const float4*)&Bs[kk][tx * 4];
                acc[0][0] = fmaf(a0, bb.x, acc[0][0]); acc[0][1] = fmaf(a0, bb.y, acc[0][1]);
                acc[0][2] = fmaf(a0, bb.z, acc[0][2]); acc[0][3] = fmaf(a0, bb.w, acc[0][3]);
                acc[1][0] = fmaf(a1, bb.x, acc[1][0]); acc[1][1] = fmaf(a1, bb.y, acc[1][1]);
                acc[1][2] = fmaf(a1, bb.z, acc[1][2]); acc[1][3] = fmaf(a1, bb.w, acc[1][3]);
            }
            __syncthreads();
        }
#pragma unroll
        for (int i = 0; i < 2; i++)
#pragma unroll
            for (int j = 0; j < 4; j++)
                g_h0[(bm + ty * 2 + i) * HID + bn + tx * 4 + j] = acc[i][j];
    }
    gbar(&g_pbar[1]);

    // ---- P2: dinv + exclusive prefix scan of cnt (CTA 0) ----
    for (int i = gt; i < NNODES; i += GT)
        g_dinv[i] = rsqrtf(fmaxf(g_deg[i], 1e-12f));
    if (b == 0) {
        unsigned loc[4], s = 0;
        const int base4 = tid * 4;
#pragma unroll
        for (int j = 0; j < 4; j++) { loc[j] = g_cnt[base4 + j]; s += loc[j]; }
        ps[tid] = s;
        __syncthreads();
        for (int d = 1; d < 512; d <<= 1) {
            unsigned v = (tid >= d) ? ps[tid - d] : 0u;
            __syncthreads();
            ps[tid] += v;
            __syncthreads();
        }
        unsigned run = tid ? ps[tid - 1] : 0u;
#pragma unroll
        for (int j = 0; j < 4; j++) {
            g_off[base4 + j] = run;
            g_pos[base4 + j] = run;
            run += loc[j];
        }
        if (tid == 511) g_off[NNODES] = run;
    }
    gbar(&g_pbar[2]);

    // ---- P3a: CSR scatter ----
    for (int e = gt; e < NEDGE; e += GT) {
        int row = ei[e], col = ei[NEDGE + e];
        float norm = g_dinv[row] * ew[e] * g_dinv[col];
        unsigned pos = atomicAdd(&g_pos[col], 1u);
        g_srow[pos] = row;
        g_snorm[pos] = norm;
    }
    gbar(&g_pbar[3]);

    // ---- P3b: atomic-free gather ----
    {
        const int n = gt >> 5;
        const int lane = tid & 31;
        const unsigned e0 = g_off[n], e1 = g_off[n + 1];
        float acc[8] = {0.f, 0.f, 0.f, 0.f, 0.f, 0.f, 0.f, 0.f};
        unsigned e = e0;
        for (; e + 2 <= e1; e += 2) {
            int r0 = g_srow[e], r1 = g_srow[e + 1];
            float n0 = g_snorm[e], n1 = g_snorm[e + 1];
            const float* h0p = g_h0 + (size_t)r0 * HID + lane;
            const float* h1p = g_h0 + (size_t)r1 * HID + lane;
#pragma unroll
            for (int j = 0; j < 8; j++) {
                float v0 = h0p[32 * j], v1 = h1p[32 * j];
                acc[j] = fmaf(n0, v0, acc[j]);
                acc[j] = fmaf(n1, v1, acc[j]);
            }
        }
        if (e < e1) {
            int r0 = g_srow[e];
            float n0 = g_snorm[e];
            const float* h0p = g_h0 + (size_t)r0 * HID + lane;
#pragma unroll
            for (int j = 0; j < 8; j++)
                acc[j] = fmaf(n0, h0p[32 * j], acc[j]);
        }
#pragma unroll
        for (int j = 0; j < 8; j++)
            g_hagg[n * HID + lane + 32 * j] = acc[j];
    }
    gbar(&g_pbar[4]);

    // ---- P4: finalize into g_htr[0] slots 1..T ----
    for (int i = gt; i < NNODES * HID; i += GT) {
        int n = i & (NNODES - 1), c = i >> 11;
        float d = g_dinv[n];
        float v = g_hagg[n * HID + c] + d * d * g_h0[n * HID + c] + gb[c];
        g_htr[0][(size_t)(1 + c) * H + n] = __float2half(fmaxf(v, 0.0f));
    }
}

// ---------------- 2) layer-0 gi GEMM (writes g_gi[0]) ----------------
#define GI_LD 72
__global__ void __launch_bounds__(256) k_gi(const float* __restrict__ B,
                                            const float* __restrict__ bih) {
    __shared__ alignas(16) __half sA[64 * GI_LD];
    __shared__ alignas(16) __half sB[128 * GI_LD];
    const int bm = blockIdx.y * 64, bn = blockIdx.x * 128;
    const int tid = threadIdx.x, lane = tid & 31, warp = tid >> 5;
    const int wm = warp >> 2, wn = warp & 3;
    float acc[2][4][4] = {};

    const int arA[2] = { tid >> 3, (tid + 256) >> 3 };
    const int acA    = (tid & 7) * 8;
    const int rB     = tid >> 4;
    const int cB     = (tid & 15) * 4;

    uint4    pA[2];
    unsigned pB[8][2];

#pragma unroll
    for (int i = 0; i < 2; i++)
        pA[i] = *(const uint4*)(g_htr[0] + (size_t)(1 + bm + arA[i]) * H + acA);
#pragma unroll
    for (int i = 0; i < 8; i++) {
        float4 v = *(const float4*)&B[(size_t)(bn + rB + 16 * i) * H + cB];
        pB[i][0] = pack_h2(v.x, v.y);
        pB[i][1] = pack_h2(v.z, v.w);
    }

    for (int it = 0; it < 32; it++) {
#pragma unroll
        for (int i = 0; i < 2; i++)
            *(uint4*)&sA[arA[i] * GI_LD + acA] = pA[i];
#pragma unroll
        for (int i = 0; i < 8; i++) {
            *(unsigned*)&sB[(rB + 16 * i) * GI_LD + cB]     = pB[i][0];
            *(unsigned*)&sB[(rB + 16 * i) * GI_LD + cB + 2] = pB[i][1];
        }
        __syncthreads();

        if (it + 1 < 32) {
            const int k0 = (it + 1) * 64;
#pragma unroll
            for (int i = 0; i < 2; i++)
                pA[i] = *(const uint4*)(g_htr[0] + (size_t)(1 + bm + arA[i]) * H + k0 + acA);
#pragma unroll
            for (int i = 0; i < 8; i++) {
                float4 v = *(const float4*)&B[(size_t)(bn + rB + 16 * i) * H + k0 + cB];
                pB[i][0] = pack_h2(v.x, v.y);
                pB[i][1] = pack_h2(v.z, v.w);
            }
        }

#pragma unroll
        for (int ks = 0; ks < 4; ks++) {
            unsigned a[2][4], bb[4][2];
#pragma unroll
            for (int mt = 0; mt < 2; mt++) {
                int r = wm * 32 + mt * 16 + (lane >> 2);
                int c = ks * 16 + (lane & 3) * 2;
                a[mt][0] = *(const unsigned*)&sA[r * GI_LD + c];
                a[mt][1] = *(const unsigned*)&sA[(r + 8) * GI_LD + c];
                a[mt][2] = *(const unsigned*)&sA[r * GI_LD + c + 8];
                a[mt][3] = *(const unsigned*)&sA[(r + 8) * GI_LD + c + 8];
            }
#pragma unroll
            for (int nt = 0; nt < 4; nt++) {
                int r = wn * 32 + nt * 8 + (lane >> 2);
                int c = ks * 16 + (lane & 3) * 2;
                bb[nt][0] = *(const unsigned*)&sB[r * GI_LD + c];
                bb[nt][1] = *(const unsigned*)&sB[r * GI_LD + c + 8];
            }
#pragma unroll
            for (int mt = 0; mt < 2; mt++)
#pragma unroll
                for (int nt = 0; nt < 4; nt++)
                    mma16816(acc[mt][nt], a[mt], bb[nt]);
        }
        __syncthreads();
    }
#pragma unroll
    for (int mt = 0; mt < 2; mt++) {
        int r0 = bm + wm * 32 + mt * 16 + (lane >> 2);
#pragma unroll
        for (int nt = 0; nt < 4; nt++) {
            int g = bn + wn * 32 + nt * 8 + (lane & 3) * 2;
            float2 bb = *(const float2*)&bih[g];
            float* c4 = acc[mt][nt];
            *(float2*)&g_gi[0][r0 * GH + g]       = make_float2(c4[0] + bb.x, c4[1] + bb.y);
            *(float2*)&g_gi[0][(r0 + 8) * GH + g] = make_float2(c4[2] + bb.x, c4[3] + bb.y);
        }
    }
}

// ------------- 3) persistent GRU scan (r12 sync) + fused next-layer gi ------------
// r12 structure: one release-RMW + one acquire-poll per CTA per step, named bars.
// Fusion (wih_next != null): CTA b holds its 48 rows of wih_{l+1} as MMA fragments
// in SMEM. Each step t>=1, warps 8-15 compute gi row t-1 (full h(t) is in sh;
// bar1-sync orders staging) in the shadow of warp 0's gates+RMW+poll; warp 1
// reduces partials (bar3) and stores to the other g_gi buffer.
__global__ void __launch_bounds__(SCAN_THREADS, 1)
k_scan(const float* __restrict__ whh, const float* __restrict__ bhh, int layer,
       int sel, const float* __restrict__ wih_next,
       const float* __restrict__ bih_next) {
    extern __shared__ char dsm[];
    uint4*  wihf = (uint4*)dsm;                               // [8][48][32]
    __half* sh   = (__half*)(dsm + SH_OFF);
    float (*spt)[48][20] = (float(*)[48][20])(dsm + SPT_OFF);
    float (*spt2)[12]    = (float(*)[12])(dsm + SPT2_OFF);

    const int b = blockIdx.x, tid = threadIdx.x;
    const int warp = tid >> 5, lane = tid & 31;
    const int qid = lane >> 2, tg = lane & 3;
    const int kbase = warp * 128;
    const int ig = b * IPB + lane;                 // valid for lane<16
    const int cp = b & (NREP - 1);
    const unsigned target = (unsigned)NBLK * (unsigned)(layer + 1);
    const int fuse = (wih_next != nullptr);
    const float* gird = g_gi[sel];
    float* giwr = g_gi[sel ^ 1];

    // ---- one-time: whh A fragments (registers) ----
    unsigned aw[8][3][4];
    {
        const int r0 = b * IPB + qid;
#pragma unroll
        for (int kt = 0; kt < 8; kt++) {
            const int c = kbase + kt * 16 + tg * 2;
#pragma unroll
            for (int g = 0; g < 3; g++) {
                const float* W0 = whh + (size_t)(g * H + r0) * H;
                const float* W1 = W0 + 8 * (size_t)H;
                float2 v;
                v = *(const float2*)(W0 + c);     aw[kt][g][0] = pack_h2(v.x, v.y);
                v = *(const float2*)(W1 + c);     aw[kt][g][1] = pack_h2(v.x, v.y);
                v = *(const float2*)(W0 + c + 8); aw[kt][g][2] = pack_h2(v.x, v.y);
                v = *(const float2*)(W1 + c + 8); aw[kt][g][3] = pack_h2(v.x, v.y);
            }
        }
    }
    // ---- one-time: next-layer wih fragments into SMEM ----
    if (fuse) {
        for (int s = tid; s < 8 * 48 * 32; s += SCAN_THREADS) {
            int lf = s & 31, grp = (s >> 5) % 48, gw = (s >> 5) / 48;
            int kt2 = grp / 3, gg = grp % 3;
            int r0 = b * IPB + (lf >> 2);
            int c = gw * 256 + kt2 * 16 + (lf & 3) * 2;
            const float* W0 = wih_next + (size_t)(gg * H + r0) * H;
            const float* W1 = W0 + 8 * (size_t)H;
            float2 v; unsigned u0, u1, u2, u3;
            v = *(const float2*)(W0 + c);     u0 = pack_h2(v.x, v.y);
            v = *(const float2*)(W1 + c);     u1 = pack_h2(v.x, v.y);
            v = *(const float2*)(W0 + c + 8); u2 = pack_h2(v.x, v.y);
            v = *(const float2*)(W1 + c + 8); u3 = pack_h2(v.x, v.y);
            wihf[s] = make_uint4(u0, u1, u2, u3);
        }
    }
    float hold = 0.0f, bR = 0.f, bZ = 0.f, bN = 0.f;
    if (warp == 0 && lane < IPB) {
        bR = bhh[ig]; bZ = bhh[H + ig]; bN = bhh[2 * H + ig];
    }
    float bN1[3] = {0.f, 0.f, 0.f};
    if (fuse && warp == 1 && lane < IPB) {
        bN1[0] = bih_next[ig]; bN1[1] = bih_next[H + ig]; bN1[2] = bih_next[2 * H + ig];
    }
    __syncthreads();

#pragma unroll 1
    for (int t = 0; t < T; t++) {
        float gir = 0.f, giz = 0.f, gin = 0.f;
        if (warp == 0 && lane < IPB) {
            const float* git = gird + (size_t)t * GH;
            gir = __ldg(git + ig); giz = __ldg(git + H + ig); gin = __ldg(git + 2 * H + ig);
        }

        // stage this warp's 128-col h slice
        {
            uint2 hv = __ldcg((const uint2*)(g_htr[cp] + (size_t)t * H + kbase) + lane);
            *((uint2*)(sh + kbase) + lane) = hv;
        }
        __syncwarp();

        float d[3][4];
#pragma unroll
        for (int g = 0; g < 3; g++) { d[g][0] = d[g][1] = d[g][2] = d[g][3] = 0.f; }
#pragma unroll
        for (int kt = 0; kt < 8; kt++) {
            unsigned bb[2];
            bb[0] = *(const unsigned*)&sh[kbase + kt * 16 + tg * 2];
            bb[1] = *(const unsigned*)&sh[kbase + kt * 16 + tg * 2 + 8];
            mma16816(d[0], aw[kt][0], bb);
            mma16816(d[1], aw[kt][1], bb);
            mma16816(d[2], aw[kt][2], bb);
        }
        const int par = t & 1;
        if (tg == 0) {
#pragma unroll
            for (int g = 0; g < 3; g++) {
                spt[par][g * 16 + qid][warp]     = d[g][0];
                spt[par][g * 16 + qid + 8][warp] = d[g][2];
            }
        }

        if (warp == 0) {
            BAR_SYNC_N(1);
            if (lane < IPB) {
                float ghr = 0.f, ghz = 0.f, ghn = 0.f;
#pragma unroll
                for (int c = 0; c < 4; c++) {
                    float4 v0 = *(const float4*)&spt[par][lane][c * 4];
                    float4 v1 = *(const float4*)&spt[par][16 + lane][c * 4];
                    float4 v2 = *(const float4*)&spt[par][32 + lane][c * 4];
                    ghr += (v0.x + v0.y) + (v0.z + v0.w);
                    ghz += (v1.x + v1.y) + (v1.z + v1.w);
                    ghn += (v2.x + v2.y) + (v2.z + v2.w);
                }
                float rr = fast_sigmoid(gir + ghr + bR);
                float zz = fast_sigmoid(giz + ghz + bZ);
                float nn = fast_tanh(gin + rr * (ghn + bN));
                float hnew = (1.0f - zz) * nn + zz * hold;
                hold = hnew;
                float other = __shfl_xor_sync(0x0000ffffu, hnew, 1);
                if (!(lane & 1)) {
                    __half2 h2 = __floats2half2_rn(hnew, other);
#pragma unroll
                    for (int c = 0; c < NREP; c++)
                        *(__half2*)(g_htr[c] + (size_t)(t + 1) * H + ig) = h2;
                }
            }
            __syncwarp();
            if (lane == 0) {
                bar_arrive(&g_bar[t + 1]);
                if (fuse || t + 1 < T) {
                    while (bar_ld_acq(&g_bar[t + 1]) < target) {}
                }
            }
            __syncwarp();
            BAR_SYNC_N(2);
        } else if (warp >= 8) {
            BAR_SYNC_N(1);             // orders all warps' staging before gi reads
            if (fuse && t >= 1) {
                const int kbase2 = (warp - 8) * 256;
                const uint4* wbase = wihf + (size_t)(warp - 8) * 48 * 32 + lane;
#pragma unroll
                for (int g = 0; g < 3; g++) { d[g][0] = d[g][1] = d[g][2] = d[g][3] = 0.f; }
#pragma unroll 4
                for (int kt = 0; kt < 16; kt++) {
                    unsigned bb[2];
                    bb[0] = *(const unsigned*)&sh[kbase2 + kt * 16 + tg * 2];
                    bb[1] = *(const unsigned*)&sh[kbase2 + kt * 16 + tg * 2 + 8];
#pragma unroll
                    for (int gg = 0; gg < 3; gg++) {
                        uint4 af = wbase[(kt * 3 + gg) * 32];
                        unsigned a4[4] = {af.x, af.y, af.z, af.w};
                        mma16816(d[gg], a4, bb);
                    }
                }
                if (tg == 0) {
#pragma unroll
                    for (int gg = 0; gg < 3; gg++) {
                        spt2[gg * 16 + qid][warp - 8]     = d[gg][0];
                        spt2[gg * 16 + qid + 8][warp - 8] = d[gg][2];
                    }
                }
                BAR3_ARRIVE();
            }
            BAR_SYNC_N(2);
        } else if (warp == 1) {
            BAR_ARRIVE_N(1);
            if (fuse && t >= 1) {
                BAR3_SYNC();
                if (lane < IPB) {
#pragma unroll
                    for (int gg = 0; gg < 3; gg++) {
                        int row = gg * 16 + lane;
                        float4 v0 = *(const float4*)&spt2[row][0];
                        float4 v1 = *(const float4*)&spt2[row][4];
                        float s = ((v0.x + v0.y) + (v0.z + v0.w))
                                + ((v1.x + v1.y) + (v1.z + v1.w));
                        giwr[(size_t)(t - 1) * GH + gg * H + ig] = s + bN1[gg];
                    }
                }
            }
            BAR_SYNC_N(2);
        } else {
            BAR_ARRIVE_N(1);
            BAR_SYNC_N(2);
        }
    }

    // ---- post-loop (fuse): gi row T-1 from slot T ----
    if (fuse) {
        {
            uint2 hv = __ldcg((const uint2*)(g_htr[cp] + (size_t)T * H + kbase) + lane);
            *((uint2*)(sh + kbase) + lane) = hv;
        }
        __syncthreads();
        if (warp >= 8) {
            const int kbase2 = (warp - 8) * 256;
            const uint4* wbase = wihf + (size_t)(warp - 8) * 48 * 32 + lane;
            float d[3][4];
#pragma unroll
            for (int g = 0; g < 3; g++) { d[g][0] = d[g][1] = d[g][2] = d[g][3] = 0.f; }
#pragma unroll 4
            for (int kt = 0; kt < 16; kt++) {
                unsigned bb[2];
                bb[0] = *(const unsigned*)&sh[kbase2 + kt * 16 + tg * 2];
                bb[1] = *(const unsigned*)&sh[kbase2 + kt * 16 + tg * 2 + 8];
#pragma unroll
                for (int gg = 0; gg < 3; gg++) {
                    uint4 af = wbase[(kt * 3 + gg) * 32];
                    unsigned a4[4] = {af.x, af.y, af.z, af.w};
                    mma16816(d[gg], a4, bb);
                }
            }
            if (tg == 0) {
#pragma unroll
                for (int gg = 0; gg < 3; gg++) {
                    spt2[gg * 16 + qid][warp - 8]     = d[gg][0];
                    spt2[gg * 16 + qid + 8][warp - 8] = d[gg][2];
                }
            }
            BAR3_ARRIVE();
        } else if (warp == 1) {
            BAR3_SYNC();
            if (lane < IPB) {
#pragma unroll
                for (int gg = 0; gg < 3; gg++) {
                    int row = gg * 16 + lane;
                    float4 v0 = *(const float4*)&spt2[row][0];
                    float4 v1 = *(const float4*)&spt2[row][4];
                    float s = ((v0.x + v0.y) + (v0.z + v0.w))
                            + ((v1.x + v1.y) + (v1.z + v1.w));
                    giwr[(size_t)(T - 1) * GH + gg * H + ig] = s + bN1[gg];
                }
            }
        }
    }
}

// ---------------- 4) final linear — 128 CTAs x 16 nodes, coalesced ----------------
__global__ void __launch_bounds__(256) k_final(const float* __restrict__ lw,
                                               const float* __restrict__ lb,
                                               float* __restrict__ out) {
    __shared__ alignas(16) __half s[T][24];
    __shared__ float slw[T * STEPA];
    const int b = blockIdx.x, tid = threadIdx.x;
    const int n0 = b * 16;

    for (int i = tid; i < T * STEPA; i += 256) slw[i] = lw[i];
    {
        const __half* src = g_htr[0] + (size_t)(tid + 1) * H + n0;
        *(uint4*)&s[tid][0] = *(const uint4*)src;
        *(uint4*)&s[tid][8] = *(const uint4*)(src + 8);
    }
    __syncthreads();

    if (tid < 16 * STEPA) {
        const int n = tid / STEPA, k = tid % STEPA;
        float a = lb[k];
#pragma unroll 8
        for (int t = 0; t < T; t++)
            a = fmaf(__half2float(s[t][n]), slw[t * STEPA + k], a);
        out[n0 * STEPA + tid] = a;
    }
}

// ---------------- launch ----------------
extern "C" void kernel_launch(void* const* d_in, const int* in_sizes, int n_in,
                              void* d_out, int out_size) {
    const float* x      = (const float*)d_in[0];
    const int*   ei     = (const int*)  d_in[1];
    const float* ew     = (const float*)d_in[2];
    const float* cnn_w  = (const float*)d_in[3];
    const float* cnn_b  = (const float*)d_in[4];
    const float* gcn_w  = (const float*)d_in[5];
    const float* gcn_b  = (const float*)d_in[6];
    const float* wih    = (const float*)d_in[7];
    const float* whh    = (const float*)d_in[8];
    const float* bih    = (const float*)d_in[9];
    const float* bhh    = (const float*)d_in[10];
    const float* lin_w  = (const float*)d_in[11];
    const float* lin_b  = (const float*)d_in[12];
    float* out = (float*)d_out;

    cudaFuncSetAttribute(k_scan, cudaFuncAttributeMaxDynamicSharedMemorySize,
                         SCAN_SMEM);

    k_zero0<<<8, 256>>>();
    k_pre<<<NBLK, PRE_THREADS>>>(x, cnn_w, cnn_b, ei, ew, gcn_w, gcn_b);

    {
        dim3 grid(GH / 128, T / 64);
        k_gi<<<grid, 256>>>(wih, bih);     // layer 0 -> g_gi[0]
    }
    // layer 0 scan reads g_gi[0], fused-computes g_gi[1] for layer 1
    k_scan<<<NBLK, SCAN_THREADS, SCAN_SMEM>>>(whh, bhh, 0, 0,
                                              wih + (size_t)1 * GH * H, bih + GH);
    // layer 1 scan reads g_gi[1], fused-computes g_gi[0] for layer 2
    k_scan<<<NBLK, SCAN_THREADS, SCAN_SMEM>>>(whh + (size_t)1 * GH * H, bhh + GH,
                                              1, 1,
                                              wih + (size_t)2 * GH * H, bih + 2 * GH);
    // layer 2 scan reads g_gi[0], no fusion
    k_scan<<<NBLK, SCAN_THREADS, SCAN_SMEM>>>(whh + (size_t)2 * GH * H, bhh + 2 * GH,
                                              2, 0, nullptr, nullptr);

    k_final<<<128, 256>>>(lin_w, lin_b, out);
}

// round 15
// speedup vs baseline: 1.0845x; 1.0845x over previous
#include <cuda_runtime.h>
#include <cuda_fp16.h>
#include <math.h>

// ---------------- problem constants ----------------
#define NNODES 2048
#define SEQ    512
#define HID    256
#define NFEAT  9
#define NEDGE  65536
#define NLAY   3
#define STEPA  14

#define H   2048          // GRU hidden = NNODES
#define T   256           // GRU time steps = HID
#define GH  6144          // 3*H

#define NBLK 128          // persistent CTAs (co-resident)
#define IPB  16           // hidden units per CTA
#define NREP 4            // h publication replicas (readers spread over copies)
#define SCAN_THREADS 512
#define PRE_THREADS  512

// ---------------- scratch (device globals; no cudaMalloc allowed) ----------------
// NOTE: __device__ globals are zero-initialized at module load, so the FIRST
// execution needs no reset kernel; k_final re-zeros the sync state for replays.
__device__ float    g_xs[NNODES*SEQ];       // conv output (n, s)
__device__ float    g_h0[NNODES*HID];       // pre-GCN h
__device__ float    g_hagg[NNODES*HID];     // GCN edge-aggregate (gather output)
__device__ float    g_deg[NNODES];
__device__ float    g_dinv[NNODES];
__device__ unsigned g_cnt[NNODES];          // per-col edge counts
__device__ unsigned g_off[NNODES+1];        // CSR offsets
__device__ unsigned g_pos[NNODES];          // scatter cursors
__device__ int      g_srow[NEDGE];          // CSR: source row per slot
__device__ float    g_snorm[NEDGE];         // CSR: edge norm per slot
__device__ float    g_gi[T*GH];             // precomputed input gates
// replicated per-step hidden states (fp16); copy 0 canonical (pre/gi/final use it)
__device__ __align__(16) __half g_htr[NREP][(T+1)*H];
__device__ unsigned g_bar[T+1];             // per-step arrival counters (monotonic)
__device__ unsigned g_pbar[8];              // phase barrier counters (preproc)

// ---------------- small helpers ----------------
__device__ __forceinline__ void bar_arrive(unsigned* p) {
    asm volatile("red.release.gpu.global.add.u32 [%0], 1;" :: "l"(p) : "memory");
}
__device__ __forceinline__ unsigned bar_ld_acq(const unsigned* p) {
    unsigned v;
    asm volatile("ld.acquire.gpu.global.u32 %0, [%1];" : "=r"(v) : "l"(p) : "memory");
    return v;
}
__device__ __forceinline__ void gbar(unsigned* ctr) {
    __syncthreads();
    if (threadIdx.x == 0) {
        bar_arrive(ctr);
        while (bar_ld_acq(ctr) < NBLK) {}
    }
    __syncthreads();
}
__device__ __forceinline__ void mma16816(float* d, const unsigned* a, const unsigned* b) {
    asm volatile("mma.sync.aligned.m16n8k16.row.col.f32.f16.f16.f32 "
                 "{%0,%1,%2,%3},{%4,%5,%6,%7},{%8,%9},{%0,%1,%2,%3};"
                 : "+f"(d[0]), "+f"(d[1]), "+f"(d[2]), "+f"(d[3])
                 : "r"(a[0]), "r"(a[1]), "r"(a[2]), "r"(a[3]),
                   "r"(b[0]), "r"(b[1]));
}
__device__ __forceinline__ unsigned pack_h2(float x, float y) {
    __half2 h = __floats2half2_rn(x, y);
    return *(unsigned*)&h;
}
// fast gates: MUFU-based, ~2^-21 rel err (vs libm sequences on the serial path)
__device__ __forceinline__ float fast_sigmoid(float x) {
    return __fdividef(1.0f, 1.0f + __expf(-x));
}
__device__ __forceinline__ float fast_tanh(float x) {
    return 1.0f - __fdividef(2.0f, __expf(2.0f * x) + 1.0f);
}
#define BAR_ARRIVE_N(id) asm volatile("bar.arrive %0, %1;" :: "r"(id), "r"(SCAN_THREADS))
#define BAR_SYNC_N(id)   asm volatile("bar.sync %0, %1;"   :: "r"(id), "r"(SCAN_THREADS) : "memory")

// ================= 1) fused preprocessing (persistent, 128 CTAs) =================
// P0 conv + init -> P1 deg/cnt atomics + gcn GEMM -> P2 dinv + prefix (CTA0)
// -> P3a CSR scatter -> P3b atomic-free gather (warp per node) -> P4 finalize
__global__ void __launch_bounds__(PRE_THREADS)
k_pre(const float* __restrict__ x,  const float* __restrict__ cw,
      const float* __restrict__ cb, const int*   __restrict__ ei,
      const float* __restrict__ ew, const float* __restrict__ gw,
      const float* __restrict__ gb) {
    __shared__ float As[16][64];
    __shared__ float Bs[16][68];   // 272B row stride: 16B-aligned rows, pad vs conflicts
    __shared__ unsigned ps[512];
    const int b = blockIdx.x, tid = threadIdx.x;
    const int gt = b * PRE_THREADS + tid;
    const int GT = NBLK * PRE_THREADS;            // 65536

    // ---- P0: 1x1 conv + deg=1 + cnt=0 ----
    {
        float bias = cb[0];
        float w[NFEAT];
#pragma unroll
        for (int f = 0; f < NFEAT; f++) w[f] = cw[f];
        const int n4 = NNODES * SEQ / 4;
        const float4* X = (const float4*)x;
        for (int i = gt; i < n4; i += GT) {
            float4 acc = make_float4(bias, bias, bias, bias);
#pragma unroll
            for (int f = 0; f < NFEAT; f++) {
                float4 v = X[(size_t)f * n4 + i];
                acc.x = fmaf(w[f], v.x, acc.x); acc.y = fmaf(w[f], v.y, acc.y);
                acc.z = fmaf(w[f], v.z, acc.z); acc.w = fmaf(w[f], v.w, acc.w);
            }
            ((float4*)g_xs)[i] = acc;
        }
        for (int i = gt; i < NNODES; i += GT) { g_deg[i] = 1.0f; g_cnt[i] = 0u; }
    }
    gbar(&g_pbar[0]);

    // ---- P1: degree + histogram atomics + h0 = xs @ gcn_w (64x64 tile/CTA) ----
    for (int e = gt; e < NEDGE; e += GT) {
        int col = ei[NEDGE + e];
        atomicAdd(&g_deg[col], ew[e]);
        atomicAdd(&g_cnt[col], 1u);
    }
    {
        const int bm = (b >> 2) * 64, bn = (b & 3) * 64;
        const int tx = tid & 15, ty = tid >> 4;
        float acc[2][4] = {};
        for (int k0 = 0; k0 < SEQ; k0 += 16) {
            {   // A: 64 rows x 16 k, transposed into As[k][m]
                int ar = tid >> 3, ac = (tid & 7) * 2;
                float2 v = *(const float2*)&g_xs[(bm + ar) * SEQ + k0 + ac];
                As[ac][ar] = v.x; As[ac + 1][ar] = v.y;
            }
            {   // B: 16 k x 64 n
                int br = tid >> 5, bc = (tid & 31) * 2;
                float2 v = *(const float2*)&gw[(k0 + br) * HID + bn + bc];
                Bs[br][bc] = v.x; Bs[br][bc + 1] = v.y;
            }
            __syncthreads();
#pragma unroll
            for (int kk = 0; kk < 16; kk++) {
                float a0 = As[kk][ty * 2], a1 = As[kk][ty * 2 + 1];
                float4 bb = *(const float4*)&Bs[kk][tx * 4];
                acc[0][0] = fmaf(a0, bb.x, acc[0][0]); acc[0][1] = fmaf(a0, bb.y, acc[0][1]);
                acc[0][2] = fmaf(a0, bb.z, acc[0][2]); acc[0][3] = fmaf(a0, bb.w, acc[0][3]);
                acc[1][0] = fmaf(a1, bb.x, acc[1][0]); acc[1][1] = fmaf(a1, bb.y, acc[1][1]);
                acc[1][2] = fmaf(a1, bb.z, acc[1][2]); acc[1][3] = fmaf(a1, bb.w, acc[1][3]);
            }
            __syncthreads();
        }
#pragma unroll
        for (int i = 0; i < 2; i++)
#pragma unroll
            for (int j = 0; j < 4; j++)
                g_h0[(bm + ty * 2 + i) * HID + bn + tx * 4 + j] = acc[i][j];
    }
    gbar(&g_pbar[1]);

    // ---- P2: dinv (all CTAs) + exclusive prefix scan of cnt (CTA 0) ----
    for (int i = gt; i < NNODES; i += GT)
        g_dinv[i] = rsqrtf(fmaxf(g_deg[i], 1e-12f));
    if (b == 0) {
        unsigned loc[4], s = 0;
        const int base4 = tid * 4;
#pragma unroll
        for (int j = 0; j < 4; j++) { loc[j] = g_cnt[base4 + j]; s += loc[j]; }
        ps[tid] = s;
        __syncthreads();
        for (int d = 1; d < 512; d <<= 1) {
            unsigned v = (tid >= d) ? ps[tid - d] : 0u;
            __syncthreads();
            ps[tid] += v;
            __syncthreads();
        }
        unsigned run = tid ? ps[tid - 1] : 0u;
#pragma unroll
        for (int j = 0; j < 4; j++) {
            g_off[base4 + j] = run;
            g_pos[base4 + j] = run;
            run += loc[j];
        }
        if (tid == 511) g_off[NNODES] = run;
    }
    gbar(&g_pbar[2]);

    // ---- P3a: CSR scatter (65K slot atomics on 2048 cursors) ----
    for (int e = gt; e < NEDGE; e += GT) {
        int row = ei[e], col = ei[NEDGE + e];
        float norm = g_dinv[row] * ew[e] * g_dinv[col];
        unsigned pos = atomicAdd(&g_pos[col], 1u);
        g_srow[pos] = row;
        g_snorm[pos] = norm;
    }
    gbar(&g_pbar[3]);

    // ---- P3b: atomic-free gather — one warp per node, register accumulation ----
    {
        const int n = gt >> 5;                 // 2048 warps -> 2048 nodes exactly
        const int lane = tid & 31;
        const unsigned e0 = g_off[n], e1 = g_off[n + 1];
        float acc[8] = {0.f, 0.f, 0.f, 0.f, 0.f, 0.f, 0.f, 0.f};
        unsigned e = e0;
        for (; e + 2 <= e1; e += 2) {          // unroll 2 for MLP
            int r0 = g_srow[e], r1 = g_srow[e + 1];
            float n0 = g_snorm[e], n1 = g_snorm[e + 1];
            const float* h0p = g_h0 + (size_t)r0 * HID + lane;
            const float* h1p = g_h0 + (size_t)r1 * HID + lane;
#pragma unroll
            for (int j = 0; j < 8; j++) {
                float v0 = h0p[32 * j], v1 = h1p[32 * j];
                acc[j] = fmaf(n0, v0, acc[j]);
                acc[j] = fmaf(n1, v1, acc[j]);
            }
        }
        if (e < e1) {
            int r0 = g_srow[e];
            float n0 = g_snorm[e];
            const float* h0p = g_h0 + (size_t)r0 * HID + lane;
#pragma unroll
            for (int j = 0; j < 8; j++)
                acc[j] = fmaf(n0, h0p[32 * j], acc[j]);
        }
#pragma unroll
        for (int j = 0; j < 8; j++)
            g_hagg[n * HID + lane + 32 * j] = acc[j];
    }
    gbar(&g_pbar[4]);

    // ---- P4: self-loop + bias + relu + transpose into g_htr[0] slots 1..T ----
    for (int i = gt; i < NNODES * HID; i += GT) {
        int n = i & (NNODES - 1), c = i >> 11;
        float d = g_dinv[n];
        float v = g_hagg[n * HID + c] + d * d * g_h0[n * HID + c] + gb[c];
        g_htr[0][(size_t)(1 + c) * H + n] = __float2half(fmaxf(v, 0.0f));
    }
}

// ---------------- 2) gi = seq @ wih.T + bih — fp16 MMA, double-buffered loads ----
// seq = g_htr[0] slots 1..T (fp16, time-major)
#define GI_LD 72
__global__ void __launch_bounds__(256) k_gi(const float* __restrict__ B,
                                            const float* __restrict__ bih) {
    __shared__ alignas(16) __half sA[64 * GI_LD];
    __shared__ alignas(16) __half sB[128 * GI_LD];
    const int bm = blockIdx.y * 64, bn = blockIdx.x * 128;
    const int tid = threadIdx.x, lane = tid & 31, warp = tid >> 5;
    const int wm = warp >> 2, wn = warp & 3;
    float acc[2][4][4] = {};

    // per-thread tile coordinates (fixed across iterations)
    const int arA[2] = { tid >> 3, (tid + 256) >> 3 };
    const int acA    = (tid & 7) * 8;
    const int rB     = tid >> 4;                       // +16*i rows
    const int cB     = (tid & 15) * 4;

    uint4    pA[2];
    unsigned pB[8][2];

    // prefetch k0 = 0
#pragma unroll
    for (int i = 0; i < 2; i++)
        pA[i] = *(const uint4*)(g_htr[0] + (size_t)(1 + bm + arA[i]) * H + acA);
#pragma unroll
    for (int i = 0; i < 8; i++) {
        float4 v = *(const float4*)&B[(size_t)(bn + rB + 16 * i) * H + cB];
        pB[i][0] = pack_h2(v.x, v.y);
        pB[i][1] = pack_h2(v.z, v.w);
    }

    for (int it = 0; it < 32; it++) {
        // store current prefetch into SMEM
#pragma unroll
        for (int i = 0; i < 2; i++)
            *(uint4*)&sA[arA[i] * GI_LD + acA] = pA[i];
#pragma unroll
        for (int i = 0; i < 8; i++) {
            *(unsigned*)&sB[(rB + 16 * i) * GI_LD + cB]     = pB[i][0];
            *(unsigned*)&sB[(rB + 16 * i) * GI_LD + cB + 2] = pB[i][1];
        }
        __syncthreads();

        // prefetch next tile (overlaps with MMA below)
        if (it + 1 < 32) {
            const int k0 = (it + 1) * 64;
#pragma unroll
            for (int i = 0; i < 2; i++)
                pA[i] = *(const uint4*)(g_htr[0] + (size_t)(1 + bm + arA[i]) * H + k0 + acA);
#pragma unroll
            for (int i = 0; i < 8; i++) {
                float4 v = *(const float4*)&B[(size_t)(bn + rB + 16 * i) * H + k0 + cB];
                pB[i][0] = pack_h2(v.x, v.y);
                pB[i][1] = pack_h2(v.z, v.w);
            }
        }

#pragma unroll
        for (int ks = 0; ks < 4; ks++) {
            unsigned a[2][4], bb[4][2];
#pragma unroll
            for (int mt = 0; mt < 2; mt++) {
                int r = wm * 32 + mt * 16 + (lane >> 2);
                int c = ks * 16 + (lane & 3) * 2;
                a[mt][0] = *(const unsigned*)&sA[r * GI_LD + c];
                a[mt][1] = *(const unsigned*)&sA[(r + 8) * GI_LD + c];
                a[mt][2] = *(const unsigned*)&sA[r * GI_LD + c + 8];
                a[mt][3] = *(const unsigned*)&sA[(r + 8) * GI_LD + c + 8];
            }
#pragma unroll
            for (int nt = 0; nt < 4; nt++) {
                int r = wn * 32 + nt * 8 + (lane >> 2);
                int c = ks * 16 + (lane & 3) * 2;
                bb[nt][0] = *(const unsigned*)&sB[r * GI_LD + c];
                bb[nt][1] = *(const unsigned*)&sB[r * GI_LD + c + 8];
            }
#pragma unroll
            for (int mt = 0; mt < 2; mt++)
#pragma unroll
                for (int nt = 0; nt < 4; nt++)
                    mma16816(acc[mt][nt], a[mt], bb[nt]);
        }
        __syncthreads();
    }
#pragma unroll
    for (int mt = 0; mt < 2; mt++) {
        int r0 = bm + wm * 32 + mt * 16 + (lane >> 2);
#pragma unroll
        for (int nt = 0; nt < 4; nt++) {
            int g = bn + wn * 32 + nt * 8 + (lane & 3) * 2;
            float2 bb = *(const float2*)&bih[g];
            float* c4 = acc[mt][nt];
            *(float2*)&g_gi[r0 * GH + g]       = make_float2(c4[0] + bb.x, c4[1] + bb.y);
            *(float2*)&g_gi[(r0 + 8) * GH + g] = make_float2(c4[2] + bb.x, c4[3] + bb.y);
        }
    }
}

// ---------------- 3) persistent GRU scan — r12 (proven best structure) -----------
// ONE release-RMW + ONE acquire-poll per CTA per step on a monotonic counter;
// named barriers inside the CTA; h published to NREP=4 replicas (consumer reads
// copy b&3); MUFU-based fast gates.
__global__ void __launch_bounds__(SCAN_THREADS, 1)
k_scan(const float* __restrict__ whh, const float* __restrict__ bhh, int layer) {
    __shared__ alignas(16) __half sh[H];
    __shared__ alignas(16) float spt[2][48][20];   // [parity][row][warp], padded

    const int b = blockIdx.x, tid = threadIdx.x;
    const int warp = tid >> 5, lane = tid & 31;
    const int qid = lane >> 2, tg = lane & 3;
    const int kbase = warp * 128;                 // this warp's K range (128 cols)
    const int ig = b * IPB + lane;                // valid for lane<16 in warp 0
    const int cp = b & (NREP - 1);                // which h replica this CTA reads
    const unsigned target = (unsigned)NBLK * (unsigned)(layer + 1);

    // ---- one-time: load this thread's A fragments (fp16) ----
    unsigned aw[8][3][4];
    {
        const int r0 = b * IPB + qid;             // rows r0, r0+8 within each gate
#pragma unroll
        for (int kt = 0; kt < 8; kt++) {
            const int c = kbase + kt * 16 + tg * 2;
#pragma unroll
            for (int g = 0; g < 3; g++) {
                const float* W0 = whh + (size_t)(g * H + r0) * H;
                const float* W1 = W0 + 8 * (size_t)H;
                float2 v;
                v = *(const float2*)(W0 + c);     aw[kt][g][0] = pack_h2(v.x, v.y);
                v = *(const float2*)(W1 + c);     aw[kt][g][1] = pack_h2(v.x, v.y);
                v = *(const float2*)(W0 + c + 8); aw[kt][g][2] = pack_h2(v.x, v.y);
                v = *(const float2*)(W1 + c + 8); aw[kt][g][3] = pack_h2(v.x, v.y);
            }
        }
    }
    // gate-thread constants + running h (fp32, pre-quantization)
    float hold = 0.0f, bR = 0.f, bZ = 0.f, bN = 0.f;
    if (warp == 0 && lane < IPB) {
        bR = bhh[ig]; bZ = bhh[H + ig]; bN = bhh[2 * H + ig];
    }

#pragma unroll 1
    for (int t = 0; t < T; t++) {
        // prefetch this step's input gates (warp 0; overlaps staging + MMA)
        float gir = 0.f, giz = 0.f, gin = 0.f;
        if (warp == 0 && lane < IPB) {
            const float* git = g_gi + (size_t)t * GH;
            gir = __ldg(git + ig); giz = __ldg(git + H + ig); gin = __ldg(git + 2 * H + ig);
        }

        // stage this warp's 128-col h slice from replica cp (readiness guaranteed
        // by the counter poll at the end of the previous iteration; slice t=0 is 0)
        {
            uint2 hv = __ldcg((const uint2*)(g_htr[cp] + (size_t)t * H + kbase) + lane);
            *((uint2*)(sh + kbase) + lane) = hv;
        }
        __syncwarp();

        float d[3][4];
#pragma unroll
        for (int g = 0; g < 3; g++) { d[g][0] = d[g][1] = d[g][2] = d[g][3] = 0.f; }
#pragma unroll
        for (int kt = 0; kt < 8; kt++) {
            unsigned bb[2];
            bb[0] = *(const unsigned*)&sh[kbase + kt * 16 + tg * 2];
            bb[1] = *(const unsigned*)&sh[kbase + kt * 16 + tg * 2 + 8];
            mma16816(d[0], aw[kt][0], bb);
            mma16816(d[1], aw[kt][1], bb);
            mma16816(d[2], aw[kt][2], bb);
        }
        const int par = t & 1;
        if (tg == 0) {
#pragma unroll
            for (int g = 0; g < 3; g++) {
                spt[par][g * 16 + qid][warp]     = d[g][0];
                spt[par][g * 16 + qid + 8][warp] = d[g][2];
            }
        }

        if (warp != 0) {
            BAR_ARRIVE_N(1);          // partials published (non-blocking)
            BAR_SYNC_N(2);            // wait until warp 0 confirms h(t+1) ready
        } else {
            BAR_SYNC_N(1);            // wait for all 16 warps' partials
            if (lane < IPB) {
                float ghr = 0.f, ghz = 0.f, ghn = 0.f;
#pragma unroll
                for (int c = 0; c < 4; c++) {
                    float4 v0 = *(const float4*)&spt[par][lane][c * 4];
                    float4 v1 = *(const float4*)&spt[par][16 + lane][c * 4];
                    float4 v2 = *(const float4*)&spt[par][32 + lane][c * 4];
                    ghr += (v0.x + v0.y) + (v0.z + v0.w);
                    ghz += (v1.x + v1.y) + (v1.z + v1.w);
                    ghn += (v2.x + v2.y) + (v2.z + v2.w);
                }
                float rr = fast_sigmoid(gir + ghr + bR);
                float zz = fast_sigmoid(giz + ghz + bZ);
                float nn = fast_tanh(gin + rr * (ghn + bN));
                float hnew = (1.0f - zz) * nn + zz * hold;
                hold = hnew;
                float other = __shfl_xor_sync(0x0000ffffu, hnew, 1);
                if (!(lane & 1)) {
                    __half2 h2 = __floats2half2_rn(hnew, other);
#pragma unroll
                    for (int c = 0; c < NREP; c++)
                        *(__half2*)(g_htr[c] + (size_t)(t + 1) * H + ig) = h2;
                }
            }
            __syncwarp();
            if (lane == 0) {
                bar_arrive(&g_bar[t + 1]);          // release: orders the h stores
                if (t + 1 < T) {
                    while (bar_ld_acq(&g_bar[t + 1]) < target) {}
                }
            }
            __syncwarp();
            BAR_ARRIVE_N(2);          // release the other 15 warps into step t+1
        }
    }
}

// ---------------- 4) final linear + replay-reset — 128 CTAs x 16 nodes -----------
__global__ void __launch_bounds__(256) k_final(const float* __restrict__ lw,
                                               const float* __restrict__ lb,
                                               float* __restrict__ out) {
    __shared__ alignas(16) __half s[T][24];   // 16 nodes + pad (48B rows, 16B-aligned)
    __shared__ float slw[T * STEPA];
    const int b = blockIdx.x, tid = threadIdx.x;
    const int n0 = b * 16;

    for (int i = tid; i < T * STEPA; i += 256) slw[i] = lw[i];
    {
        const __half* src = g_htr[0] + (size_t)(tid + 1) * H + n0;
        *(uint4*)&s[tid][0] = *(const uint4*)src;
        *(uint4*)&s[tid][8] = *(const uint4*)(src + 8);
    }
    __syncthreads();

    if (tid < 16 * STEPA) {
        const int n = tid / STEPA, k = tid % STEPA;
        float a = lb[k];
#pragma unroll 8
        for (int t = 0; t < T; t++)
            a = fmaf(__half2float(s[t][n]), slw[t * STEPA + k], a);
        out[n0 * STEPA + tid] = a;     // (n0+n)*14 + k == n0*14 + tid: coalesced
    }

    // ---- replay-safe reset for the NEXT graph replay (no extra launch) ----
    // Slot-0 of g_htr is not read by this kernel (it reads slots 1..T), and the
    // counters are not read here, so these writes race with nothing.
    if (tid < IPB) {           // zero this CTA's 16 nodes of h(0), all replicas
#pragma unroll
        for (int c = 0; c < NREP; c++)
            g_htr[c][n0 + tid] = __float2half(0.0f);
    }
    if (b == 0) {              // CTA 0 resets the sync counters
        for (int i = tid; i <= T; i += 256) g_bar[i] = 0u;
        if (tid < 8) g_pbar[tid] = 0u;
    }
}

// ---------------- launch ----------------
extern "C" void kernel_launch(void* const* d_in, const int* in_sizes, int n_in,
                              void* d_out, int out_size) {
    const float* x      = (const float*)d_in[0];
    const int*   ei     = (const int*)  d_in[1];
    const float* ew     = (const float*)d_in[2];
    const float* cnn_w  = (const float*)d_in[3];
    const float* cnn_b  = (const float*)d_in[4];
    const float* gcn_w  = (const float*)d_in[5];
    const float* gcn_b  = (const float*)d_in[6];
    const float* wih    = (const float*)d_in[7];
    const float* whh    = (const float*)d_in[8];
    const float* bih    = (const float*)d_in[9];
    const float* bhh    = (const float*)d_in[10];
    const float* lin_w  = (const float*)d_in[11];
    const float* lin_b  = (const float*)d_in[12];
    float* out = (float*)d_out;

    // First run relies on zero-initialized __device__ globals; k_final resets
    // the sync state at the end of every run for graph replays.
    k_pre<<<NBLK, PRE_THREADS>>>(x, cnn_w, cnn_b, ei, ew, gcn_w, gcn_b);

    for (int l = 0; l < NLAY; l++) {
        dim3 grid(GH / 128, T / 64);
        k_gi<<<grid, 256>>>(wih + (size_t)l * GH * H, bih + l * GH);
        k_scan<<<NBLK, SCAN_THREADS>>>(whh + (size_t)l * GH * H, bhh + l * GH, l);
    }

    k_final<<<128, 256>>>(lin_w, lin_b, out);
}

// round 16
// speedup vs baseline: 1.0923x; 1.0072x over previous
#include <cuda_runtime.h>
#include <cuda_fp16.h>
#include <math.h>

// ---------------- problem constants ----------------
#define NNODES 2048
#define SEQ    512
#define HID    256
#define NFEAT  9
#define NEDGE  65536
#define NLAY   3
#define STEPA  14

#define H   2048          // GRU hidden = NNODES
#define T   256           // GRU time steps = HID
#define GH  6144          // 3*H

#define NBLK 128          // persistent CTAs (co-resident)
#define IPB  16           // hidden units per CTA
#define NREP 4            // h publication replicas (readers spread over copies)
#define SCAN_THREADS 512
#define PRE_THREADS  512

// ---------------- scratch (device globals; no cudaMalloc allowed) ----------------
// NOTE: __device__ globals are zero-initialized at module load, so the FIRST
// execution needs no reset kernel; k_final re-zeros the sync state for replays.
__device__ float    g_xs[NNODES*SEQ];       // conv output (n, s)
__device__ float    g_h0[NNODES*HID];       // pre-GCN h
__device__ float    g_hagg[NNODES*HID];     // GCN edge-aggregate (gather output)
__device__ float    g_deg[NNODES];
__device__ float    g_dinv[NNODES];
__device__ unsigned g_cnt[NNODES];          // per-col edge counts
__device__ unsigned g_off[NNODES+1];        // CSR offsets
__device__ unsigned g_pos[NNODES];          // scatter cursors
__device__ int      g_srow[NEDGE];          // CSR: source row per slot
__device__ float    g_snorm[NEDGE];         // CSR: edge norm per slot
__device__ float    g_gi[T*GH];             // precomputed input gates
// replicated per-step hidden states (fp16); copy 0 canonical (pre/gi/final use it)
__device__ __align__(16) __half g_htr[NREP][(T+1)*H];
__device__ unsigned g_bar[T+1];             // per-step arrival counters (monotonic)
__device__ unsigned g_pbar[8];              // phase barrier counters (preproc)

// ---------------- small helpers ----------------
__device__ __forceinline__ void bar_arrive(unsigned* p) {
    asm volatile("red.release.gpu.global.add.u32 [%0], 1;" :: "l"(p) : "memory");
}
__device__ __forceinline__ unsigned bar_ld_acq(const unsigned* p) {
    unsigned v;
    asm volatile("ld.acquire.gpu.global.u32 %0, [%1];" : "=r"(v) : "l"(p) : "memory");
    return v;
}
__device__ __forceinline__ void gbar(unsigned* ctr) {
    __syncthreads();
    if (threadIdx.x == 0) {
        bar_arrive(ctr);
        while (bar_ld_acq(ctr) < NBLK) {}
    }
    __syncthreads();
}
__device__ __forceinline__ void mma16816(float* d, const unsigned* a, const unsigned* b) {
    asm volatile("mma.sync.aligned.m16n8k16.row.col.f32.f16.f16.f32 "
                 "{%0,%1,%2,%3},{%4,%5,%6,%7},{%8,%9},{%0,%1,%2,%3};"
                 : "+f"(d[0]), "+f"(d[1]), "+f"(d[2]), "+f"(d[3])
                 : "r"(a[0]), "r"(a[1]), "r"(a[2]), "r"(a[3]),
                   "r"(b[0]), "r"(b[1]));
}
__device__ __forceinline__ unsigned pack_h2(float x, float y) {
    __half2 h = __floats2half2_rn(x, y);
    return *(unsigned*)&h;
}
// fast gates: MUFU-based, ~2^-21 rel err (vs libm sequences on the serial path)
__device__ __forceinline__ float fast_sigmoid(float x) {
    return __fdividef(1.0f, 1.0f + __expf(-x));
}
__device__ __forceinline__ float fast_tanh(float x) {
    return 1.0f - __fdividef(2.0f, __expf(2.0f * x) + 1.0f);
}
#define BAR_ARRIVE_N(id) asm volatile("bar.arrive %0, %1;" :: "r"(id), "r"(SCAN_THREADS))
#define BAR_SYNC_N(id)   asm volatile("bar.sync %0, %1;"   :: "r"(id), "r"(SCAN_THREADS) : "memory")

// ================= 1) fused preprocessing (persistent, 128 CTAs) =================
// P0 conv + init -> P1 deg/cnt atomics + gcn GEMM -> P2 dinv + prefix (CTA0)
// -> P3a CSR scatter -> P3b atomic-free gather (warp per node) -> P4 finalize
__global__ void __launch_bounds__(PRE_THREADS)
k_pre(const float* __restrict__ x,  const float* __restrict__ cw,
      const float* __restrict__ cb, const int*   __restrict__ ei,
      const float* __restrict__ ew, const float* __restrict__ gw,
      const float* __restrict__ gb) {
    __shared__ float As[16][64];
    __shared__ float Bs[16][68];   // 272B row stride: 16B-aligned rows, pad vs conflicts
    __shared__ unsigned ps[512];
    const int b = blockIdx.x, tid = threadIdx.x;
    const int gt = b * PRE_THREADS + tid;
    const int GT = NBLK * PRE_THREADS;            // 65536

    // ---- P0: 1x1 conv + deg=1 + cnt=0 ----
    {
        float bias = cb[0];
        float w[NFEAT];
#pragma unroll
        for (int f = 0; f < NFEAT; f++) w[f] = cw[f];
        const int n4 = NNODES * SEQ / 4;
        const float4* X = (const float4*)x;
        for (int i = gt; i < n4; i += GT) {
            float4 acc = make_float4(bias, bias, bias, bias);
#pragma unroll
            for (int f = 0; f < NFEAT; f++) {
                float4 v = X[(size_t)f * n4 + i];
                acc.x = fmaf(w[f], v.x, acc.x); acc.y = fmaf(w[f], v.y, acc.y);
                acc.z = fmaf(w[f], v.z, acc.z); acc.w = fmaf(w[f], v.w, acc.w);
            }
            ((float4*)g_xs)[i] = acc;
        }
        for (int i = gt; i < NNODES; i += GT) { g_deg[i] = 1.0f; g_cnt[i] = 0u; }
    }
    gbar(&g_pbar[0]);

    // ---- P1: degree + histogram atomics + h0 = xs @ gcn_w (64x64 tile/CTA) ----
    for (int e = gt; e < NEDGE; e += GT) {
        int col = ei[NEDGE + e];
        atomicAdd(&g_deg[col], ew[e]);
        atomicAdd(&g_cnt[col], 1u);
    }
    {
        const int bm = (b >> 2) * 64, bn = (b & 3) * 64;
        const int tx = tid & 15, ty = tid >> 4;
        float acc[2][4] = {};
        for (int k0 = 0; k0 < SEQ; k0 += 16) {
            {   // A: 64 rows x 16 k, transposed into As[k][m]
                int ar = tid >> 3, ac = (tid & 7) * 2;
                float2 v = *(const float2*)&g_xs[(bm + ar) * SEQ + k0 + ac];
                As[ac][ar] = v.x; As[ac + 1][ar] = v.y;
            }
            {   // B: 16 k x 64 n
                int br = tid >> 5, bc = (tid & 31) * 2;
                float2 v = *(const float2*)&gw[(k0 + br) * HID + bn + bc];
                Bs[br][bc] = v.x; Bs[br][bc + 1] = v.y;
            }
            __syncthreads();
#pragma unroll
            for (int kk = 0; kk < 16; kk++) {
                float a0 = As[kk][ty * 2], a1 = As[kk][ty * 2 + 1];
                float4 bb = *(const float4*)&Bs[kk][tx * 4];
                acc[0][0] = fmaf(a0, bb.x, acc[0][0]); acc[0][1] = fmaf(a0, bb.y, acc[0][1]);
                acc[0][2] = fmaf(a0, bb.z, acc[0][2]); acc[0][3] = fmaf(a0, bb.w, acc[0][3]);
                acc[1][0] = fmaf(a1, bb.x, acc[1][0]); acc[1][1] = fmaf(a1, bb.y, acc[1][1]);
                acc[1][2] = fmaf(a1, bb.z, acc[1][2]); acc[1][3] = fmaf(a1, bb.w, acc[1][3]);
            }
            __syncthreads();
        }
#pragma unroll
        for (int i = 0; i < 2; i++)
#pragma unroll
            for (int j = 0; j < 4; j++)
                g_h0[(bm + ty * 2 + i) * HID + bn + tx * 4 + j] = acc[i][j];
    }
    gbar(&g_pbar[1]);

    // ---- P2: dinv (all CTAs) + exclusive prefix scan of cnt (CTA 0) ----
    for (int i = gt; i < NNODES; i += GT)
        g_dinv[i] = rsqrtf(fmaxf(g_deg[i], 1e-12f));
    if (b == 0) {
        unsigned loc[4], s = 0;
        const int base4 = tid * 4;
#pragma unroll
        for (int j = 0; j < 4; j++) { loc[j] = g_cnt[base4 + j]; s += loc[j]; }
        ps[tid] = s;
        __syncthreads();
        for (int d = 1; d < 512; d <<= 1) {
            unsigned v = (tid >= d) ? ps[tid - d] : 0u;
            __syncthreads();
            ps[tid] += v;
            __syncthreads();
        }
        unsigned run = tid ? ps[tid - 1] : 0u;
#pragma unroll
        for (int j = 0; j < 4; j++) {
            g_off[base4 + j] = run;
            g_pos[base4 + j] = run;
            run += loc[j];
        }
        if (tid == 511) g_off[NNODES] = run;
    }
    gbar(&g_pbar[2]);

    // ---- P3a: CSR scatter (65K slot atomics on 2048 cursors) ----
    for (int e = gt; e < NEDGE; e += GT) {
        int row = ei[e], col = ei[NEDGE + e];
        float norm = g_dinv[row] * ew[e] * g_dinv[col];
        unsigned pos = atomicAdd(&g_pos[col], 1u);
        g_srow[pos] = row;
        g_snorm[pos] = norm;
    }
    gbar(&g_pbar[3]);

    // ---- P3b: atomic-free gather — one warp per node, register accumulation ----
    {
        const int n = gt >> 5;                 // 2048 warps -> 2048 nodes exactly
        const int lane = tid & 31;
        const unsigned e0 = g_off[n], e1 = g_off[n + 1];
        float acc[8] = {0.f, 0.f, 0.f, 0.f, 0.f, 0.f, 0.f, 0.f};
        unsigned e = e0;
        for (; e + 2 <= e1; e += 2) {          // unroll 2 for MLP
            int r0 = g_srow[e], r1 = g_srow[e + 1];
            float n0 = g_snorm[e], n1 = g_snorm[e + 1];
            const float* h0p = g_h0 + (size_t)r0 * HID + lane;
            const float* h1p = g_h0 + (size_t)r1 * HID + lane;
#pragma unroll
            for (int j = 0; j < 8; j++) {
                float v0 = h0p[32 * j], v1 = h1p[32 * j];
                acc[j] = fmaf(n0, v0, acc[j]);
                acc[j] = fmaf(n1, v1, acc[j]);
            }
        }
        if (e < e1) {
            int r0 = g_srow[e];
            float n0 = g_snorm[e];
            const float* h0p = g_h0 + (size_t)r0 * HID + lane;
#pragma unroll
            for (int j = 0; j < 8; j++)
                acc[j] = fmaf(n0, h0p[32 * j], acc[j]);
        }
#pragma unroll
        for (int j = 0; j < 8; j++)
            g_hagg[n * HID + lane + 32 * j] = acc[j];
    }
    gbar(&g_pbar[4]);

    // ---- P4: self-loop + bias + relu + transpose into g_htr[0] slots 1..T ----
    for (int i = gt; i < NNODES * HID; i += GT) {
        int n = i & (NNODES - 1), c = i >> 11;
        float d = g_dinv[n];
        float v = g_hagg[n * HID + c] + d * d * g_h0[n * HID + c] + gb[c];
        g_htr[0][(size_t)(1 + c) * H + n] = __float2half(fmaxf(v, 0.0f));
    }
}

// ---------------- 2) gi = seq @ wih.T + bih — fp16 MMA, occupancy-tiled ----------
// seq = g_htr[0] slots 1..T (fp16, time-major).
// BM=64, BN=64, 128 threads (4 warps, 2Mx2N, warp tile 32x32), grid (96,4)=384
// CTAs (~2.6/SM, up to 5 co-resident) so DRAM latency on the wih stream is
// hidden by cross-CTA parallelism instead of a single CTA's prefetch depth.
#define GI_LD 72
__global__ void __launch_bounds__(128) k_gi(const float* __restrict__ B,
                                            const float* __restrict__ bih) {
    __shared__ alignas(16) __half sA[64 * GI_LD];
    __shared__ alignas(16) __half sB[64 * GI_LD];
    const int bm = blockIdx.y * 64, bn = blockIdx.x * 64;
    const int tid = threadIdx.x, lane = tid & 31, warp = tid >> 5;
    const int wm = warp >> 1, wn = warp & 1;
    float acc[2][4][4] = {};

    // per-thread tile coordinates (fixed across iterations)
    const int rA = tid >> 3;                           // +16*i rows (i<4)
    const int acA = (tid & 7) * 8;                     // 8 halves (one uint4)
    const int rB = tid >> 4;                           // +8*i rows (i<8)
    const int cB = (tid & 15) * 4;                     // 4 floats

    uint4    pA[4];
    unsigned pB[8][2];

    // prefetch k0 = 0
#pragma unroll
    for (int i = 0; i < 4; i++)
        pA[i] = *(const uint4*)(g_htr[0] + (size_t)(1 + bm + rA + 16 * i) * H + acA);
#pragma unroll
    for (int i = 0; i < 8; i++) {
        float4 v = *(const float4*)&B[(size_t)(bn + rB + 8 * i) * H + cB];
        pB[i][0] = pack_h2(v.x, v.y);
        pB[i][1] = pack_h2(v.z, v.w);
    }

    for (int it = 0; it < 32; it++) {
        // store current prefetch into SMEM
#pragma unroll
        for (int i = 0; i < 4; i++)
            *(uint4*)&sA[(rA + 16 * i) * GI_LD + acA] = pA[i];
#pragma unroll
        for (int i = 0; i < 8; i++) {
            *(unsigned*)&sB[(rB + 8 * i) * GI_LD + cB]     = pB[i][0];
            *(unsigned*)&sB[(rB + 8 * i) * GI_LD + cB + 2] = pB[i][1];
        }
        __syncthreads();

        // prefetch next tile (overlaps with MMA below)
        if (it + 1 < 32) {
            const int k0 = (it + 1) * 64;
#pragma unroll
            for (int i = 0; i < 4; i++)
                pA[i] = *(const uint4*)(g_htr[0] + (size_t)(1 + bm + rA + 16 * i) * H + k0 + acA);
#pragma unroll
            for (int i = 0; i < 8; i++) {
                float4 v = *(const float4*)&B[(size_t)(bn + rB + 8 * i) * H + k0 + cB];
                pB[i][0] = pack_h2(v.x, v.y);
                pB[i][1] = pack_h2(v.z, v.w);
            }
        }

#pragma unroll
        for (int ks = 0; ks < 4; ks++) {
            unsigned a[2][4], bb[4][2];
#pragma unroll
            for (int mt = 0; mt < 2; mt++) {
                int r = wm * 32 + mt * 16 + (lane >> 2);
                int c = ks * 16 + (lane & 3) * 2;
                a[mt][0] = *(const unsigned*)&sA[r * GI_LD + c];
                a[mt][1] = *(const unsigned*)&sA[(r + 8) * GI_LD + c];
                a[mt][2] = *(const unsigned*)&sA[r * GI_LD + c + 8];
                a[mt][3] = *(const unsigned*)&sA[(r + 8) * GI_LD + c + 8];
            }
#pragma unroll
            for (int nt = 0; nt < 4; nt++) {
                int r = wn * 32 + nt * 8 + (lane >> 2);
                int c = ks * 16 + (lane & 3) * 2;
                bb[nt][0] = *(const unsigned*)&sB[r * GI_LD + c];
                bb[nt][1] = *(const unsigned*)&sB[r * GI_LD + c + 8];
            }
#pragma unroll
            for (int mt = 0; mt < 2; mt++)
#pragma unroll
                for (int nt = 0; nt < 4; nt++)
                    mma16816(acc[mt][nt], a[mt], bb[nt]);
        }
        __syncthreads();
    }
#pragma unroll
    for (int mt = 0; mt < 2; mt++) {
        int r0 = bm + wm * 32 + mt * 16 + (lane >> 2);
#pragma unroll
        for (int nt = 0; nt < 4; nt++) {
            int g = bn + wn * 32 + nt * 8 + (lane & 3) * 2;
            float2 bb = *(const float2*)&bih[g];
            float* c4 = acc[mt][nt];
            *(float2*)&g_gi[r0 * GH + g]       = make_float2(c4[0] + bb.x, c4[1] + bb.y);
            *(float2*)&g_gi[(r0 + 8) * GH + g] = make_float2(c4[2] + bb.x, c4[3] + bb.y);
        }
    }
}

// ---------------- 3) persistent GRU scan — r12 (proven best structure) -----------
// ONE release-RMW + ONE acquire-poll per CTA per step on a monotonic counter;
// named barriers inside the CTA; h published to NREP=4 replicas (consumer reads
// copy b&3); MUFU-based fast gates.
__global__ void __launch_bounds__(SCAN_THREADS, 1)
k_scan(const float* __restrict__ whh, const float* __restrict__ bhh, int layer) {
    __shared__ alignas(16) __half sh[H];
    __shared__ alignas(16) float spt[2][48][20];   // [parity][row][warp], padded

    const int b = blockIdx.x, tid = threadIdx.x;
    const int warp = tid >> 5, lane = tid & 31;
    const int qid = lane >> 2, tg = lane & 3;
    const int kbase = warp * 128;                 // this warp's K range (128 cols)
    const int ig = b * IPB + lane;                // valid for lane<16 in warp 0
    const int cp = b & (NREP - 1);                // which h replica this CTA reads
    const unsigned target = (unsigned)NBLK * (unsigned)(layer + 1);

    // ---- one-time: load this thread's A fragments (fp16) ----
    unsigned aw[8][3][4];
    {
        const int r0 = b * IPB + qid;             // rows r0, r0+8 within each gate
#pragma unroll
        for (int kt = 0; kt < 8; kt++) {
            const int c = kbase + kt * 16 + tg * 2;
#pragma unroll
            for (int g = 0; g < 3; g++) {
                const float* W0 = whh + (size_t)(g * H + r0) * H;
                const float* W1 = W0 + 8 * (size_t)H;
                float2 v;
                v = *(const float2*)(W0 + c);     aw[kt][g][0] = pack_h2(v.x, v.y);
                v = *(const float2*)(W1 + c);     aw[kt][g][1] = pack_h2(v.x, v.y);
                v = *(const float2*)(W0 + c + 8); aw[kt][g][2] = pack_h2(v.x, v.y);
                v = *(const float2*)(W1 + c + 8); aw[kt][g][3] = pack_h2(v.x, v.y);
            }
        }
    }
    // gate-thread constants + running h (fp32, pre-quantization)
    float hold = 0.0f, bR = 0.f, bZ = 0.f, bN = 0.f;
    if (warp == 0 && lane < IPB) {
        bR = bhh[ig]; bZ = bhh[H + ig]; bN = bhh[2 * H + ig];
    }

#pragma unroll 1
    for (int t = 0; t < T; t++) {
        // prefetch this step's input gates (warp 0; overlaps staging + MMA)
        float gir = 0.f, giz = 0.f, gin = 0.f;
        if (warp == 0 && lane < IPB) {
            const float* git = g_gi + (size_t)t * GH;
            gir = __ldg(git + ig); giz = __ldg(git + H + ig); gin = __ldg(git + 2 * H + ig);
        }

        // stage this warp's 128-col h slice from replica cp (readiness guaranteed
        // by the counter poll at the end of the previous iteration; slice t=0 is 0)
        {
            uint2 hv = __ldcg((const uint2*)(g_htr[cp] + (size_t)t * H + kbase) + lane);
            *((uint2*)(sh + kbase) + lane) = hv;
        }
        __syncwarp();

        float d[3][4];
#pragma unroll
        for (int g = 0; g < 3; g++) { d[g][0] = d[g][1] = d[g][2] = d[g][3] = 0.f; }
#pragma unroll
        for (int kt = 0; kt < 8; kt++) {
            unsigned bb[2];
            bb[0] = *(const unsigned*)&sh[kbase + kt * 16 + tg * 2];
            bb[1] = *(const unsigned*)&sh[kbase + kt * 16 + tg * 2 + 8];
            mma16816(d[0], aw[kt][0], bb);
            mma16816(d[1], aw[kt][1], bb);
            mma16816(d[2], aw[kt][2], bb);
        }
        const int par = t & 1;
        if (tg == 0) {
#pragma unroll
            for (int g = 0; g < 3; g++) {
                spt[par][g * 16 + qid][warp]     = d[g][0];
                spt[par][g * 16 + qid + 8][warp] = d[g][2];
            }
        }

        if (warp != 0) {
            BAR_ARRIVE_N(1);          // partials published (non-blocking)
            BAR_SYNC_N(2);            // wait until warp 0 confirms h(t+1) ready
        } else {
            BAR_SYNC_N(1);            // wait for all 16 warps' partials
            if (lane < IPB) {
                float ghr = 0.f, ghz = 0.f, ghn = 0.f;
#pragma unroll
                for (int c = 0; c < 4; c++) {
                    float4 v0 = *(const float4*)&spt[par][lane][c * 4];
                    float4 v1 = *(const float4*)&spt[par][16 + lane][c * 4];
                    float4 v2 = *(const float4*)&spt[par][32 + lane][c * 4];
                    ghr += (v0.x + v0.y) + (v0.z + v0.w);
                    ghz += (v1.x + v1.y) + (v1.z + v1.w);
                    ghn += (v2.x + v2.y) + (v2.z + v2.w);
                }
                float rr = fast_sigmoid(gir + ghr + bR);
                float zz = fast_sigmoid(giz + ghz + bZ);
                float nn = fast_tanh(gin + rr * (ghn + bN));
                float hnew = (1.0f - zz) * nn + zz * hold;
                hold = hnew;
                float other = __shfl_xor_sync(0x0000ffffu, hnew, 1);
                if (!(lane & 1)) {
                    __half2 h2 = __floats2half2_rn(hnew, other);
#pragma unroll
                    for (int c = 0; c < NREP; c++)
                        *(__half2*)(g_htr[c] + (size_t)(t + 1) * H + ig) = h2;
                }
            }
            __syncwarp();
            if (lane == 0) {
                bar_arrive(&g_bar[t + 1]);          // release: orders the h stores
                if (t + 1 < T) {
                    while (bar_ld_acq(&g_bar[t + 1]) < target) {}
                }
            }
            __syncwarp();
            BAR_ARRIVE_N(2);          // release the other 15 warps into step t+1
        }
    }
}

// ---------------- 4) final linear + replay-reset — 128 CTAs x 16 nodes -----------
__global__ void __launch_bounds__(256) k_final(const float* __restrict__ lw,
                                               const float* __restrict__ lb,
                                               float* __restrict__ out) {
    __shared__ alignas(16) __half s[T][24];   // 16 nodes + pad (48B rows, 16B-aligned)
    __shared__ float slw[T * STEPA];
    const int b = blockIdx.x, tid = threadIdx.x;
    const int n0 = b * 16;

    for (int i = tid; i < T * STEPA; i += 256) slw[i] = lw[i];
    {
        const __half* src = g_htr[0] + (size_t)(tid + 1) * H + n0;
        *(uint4*)&s[tid][0] = *(const uint4*)src;
        *(uint4*)&s[tid][8] = *(const uint4*)(src + 8);
    }
    __syncthreads();

    if (tid < 16 * STEPA) {
        const int n = tid / STEPA, k = tid % STEPA;
        float a = lb[k];
#pragma unroll 8
        for (int t = 0; t < T; t++)
            a = fmaf(__half2float(s[t][n]), slw[t * STEPA + k], a);
        out[n0 * STEPA + tid] = a;     // (n0+n)*14 + k == n0*14 + tid: coalesced
    }

    // ---- replay-safe reset for the NEXT graph replay (no extra launch) ----
    // Slot-0 of g_htr is not read by this kernel (it reads slots 1..T), and the
    // counters are not read here, so these writes race with nothing.
    if (tid < IPB) {           // zero this CTA's 16 nodes of h(0), all replicas
#pragma unroll
        for (int c = 0; c < NREP; c++)
            g_htr[c][n0 + tid] = __float2half(0.0f);
    }
    if (b == 0) {              // CTA 0 resets the sync counters
        for (int i = tid; i <= T; i += 256) g_bar[i] = 0u;
        if (tid < 8) g_pbar[tid] = 0u;
    }
}

// ---------------- launch ----------------
extern "C" void kernel_launch(void* const* d_in, const int* in_sizes, int n_in,
                              void* d_out, int out_size) {
    const float* x      = (const float*)d_in[0];
    const int*   ei     = (const int*)  d_in[1];
    const float* ew     = (const float*)d_in[2];
    const float* cnn_w  = (const float*)d_in[3];
    const float* cnn_b  = (const float*)d_in[4];
    const float* gcn_w  = (const float*)d_in[5];
    const float* gcn_b  = (const float*)d_in[6];
    const float* wih    = (const float*)d_in[7];
    const float* whh    = (const float*)d_in[8];
    const float* bih    = (const float*)d_in[9];
    const float* bhh    = (const float*)d_in[10];
    const float* lin_w  = (const float*)d_in[11];
    const float* lin_b  = (const float*)d_in[12];
    float* out = (float*)d_out;

    // First run relies on zero-initialized __device__ globals; k_final resets
    // the sync state at the end of every run for graph replays.
    k_pre<<<NBLK, PRE_THREADS>>>(x, cnn_w, cnn_b, ei, ew, gcn_w, gcn_b);

    for (int l = 0; l < NLAY; l++) {
        dim3 grid(GH / 64, T / 64);
        k_gi<<<grid, 128>>>(wih + (size_t)l * GH * H, bih + l * GH);
        k_scan<<<NBLK, SCAN_THREADS>>>(whh + (size_t)l * GH * H, bhh + l * GH, l);
    }

    k_final<<<128, 256>>>(lin_w, lin_b, out);
}